// round 2
// baseline (speedup 1.0000x reference)
#include <cuda_runtime.h>
#include <math.h>

#define Bn 16
#define Cn 64
#define Hn 256
#define HWn 65536

__device__ float g_x[Bn*Cn*HWn];       // activations [b][c][h][w] (updated in place)
__device__ float g_G[Bn*Cn*Hn*32];     // fwd w-DFT: [row][kx][2]
__device__ float g_F[Bn*Cn*1024];      // fwd spectrum [bc][s][kx][2]
__device__ float g_F2[Bn*Cn*1024];     // after spectral mix [bo][s][kx][2]
__device__ float g_Gi[Bn*Cn*8192];     // inv h-DFT [bo][kx*2+ri][h]
__device__ float g_part[Bn*Cn*Hn];     // proj partial sums per (b,o,h)
__device__ float g_ct[256];
__device__ float g_st[256];

__device__ __forceinline__ float gelu(float x) {
    return 0.5f * x * (1.0f + erff(x * 0.70710678f));
}

__global__ void k_twiddle() {
    int n = threadIdx.x;
    double s, c;
    sincospi((double)n / 128.0, &s, &c);   // 2*pi*n/256
    g_ct[n] = (float)c;  g_st[n] = (float)s;
}

__global__ void __launch_bounds__(256) k_lift(const float* __restrict__ grid,
                                              const float* __restrict__ lw,
                                              const float* __restrict__ lb) {
    __shared__ float sw[960], sb[64];
    for (int i = threadIdx.x; i < 960; i += 256) sw[i] = lw[i];
    if (threadIdx.x < 64) sb[threadIdx.x] = lb[threadIdx.x];
    __syncthreads();
    int p = blockIdx.x * 256 + threadIdx.x;
    int b = p >> 16, hw = p & 65535;
    float in[15];
    const float* gp = grid + b * 15 * HWn + hw;
    #pragma unroll
    for (int c = 0; c < 15; c++) in[c] = gp[c * HWn];
    float* xp = g_x + b * Cn * HWn + hw;
    for (int o = 0; o < 64; o++) {
        float a = sb[o];
        #pragma unroll
        for (int c = 0; c < 15; c++) a = fmaf(in[c], sw[o * 15 + c], a);
        xp[o * HWn] = gelu(a);
    }
}

// rows of 256 -> 16 complex kx modes. 64 rows/block, 128 thr = 8 row-groups x 16 kx
__global__ void __launch_bounds__(128) k_fwd_w() {
    extern __shared__ float xs[];                 // [64][257]
    int tid = threadIdx.x, r0 = blockIdx.x * 64;
    for (int i = tid; i < 64 * 256; i += 128)
        xs[(i >> 8) * 257 + (i & 255)] = g_x[(r0 + (i >> 8)) * 256 + (i & 255)];
    __syncthreads();
    int kx = tid & 15, rq = tid >> 4;
    float cd = g_ct[kx], sd = -g_st[kx], cw = 1.f, sw = 0.f;
    float ar[8], ai[8];
    #pragma unroll
    for (int i = 0; i < 8; i++) { ar[i] = 0.f; ai[i] = 0.f; }
    const float* xr = xs + rq * 8 * 257;
    for (int w = 0; w < 256; w++) {
        #pragma unroll
        for (int i = 0; i < 8; i++) {
            float x = xr[i * 257 + w];
            ar[i] = fmaf(x, cw, ar[i]);
            ai[i] = fmaf(x, sw, ai[i]);
        }
        float cn = cw * cd - sw * sd;
        sw = fmaf(cw, sd, sw * cd);  cw = cn;
    }
    #pragma unroll
    for (int i = 0; i < 8; i++) {
        int r = r0 + rq * 8 + i;
        g_G[r * 32 + kx * 2]     = ar[i];
        g_G[r * 32 + kx * 2 + 1] = ai[i];
    }
}

// 256 h -> 32 ky modes. block per (b,c); 256 thr = 32 s x 8 kx-pairs
__global__ void __launch_bounds__(256) k_fwd_h() {
    __shared__ float Gs[8192];
    int tid = threadIdx.x, bc = blockIdx.x;
    const float* gp = g_G + bc * 8192;
    for (int i = tid; i < 8192; i += 256) Gs[i] = gp[i];
    __syncthreads();
    int s = tid >> 3, kq = tid & 7;
    int ky = (s < 16) ? s : s + 224;
    float cd = g_ct[ky], sd = -g_st[ky], cw = 1.f, sw = 0.f;
    float fr0 = 0.f, fi0 = 0.f, fr1 = 0.f, fi1 = 0.f;
    for (int h = 0; h < 256; h++) {
        float2 g0 = *(const float2*)&Gs[h * 32 + kq * 4];
        float2 g1 = *(const float2*)&Gs[h * 32 + kq * 4 + 2];
        fr0 = fmaf(g0.x, cw, fmaf(-g0.y, sw, fr0));
        fi0 = fmaf(g0.y, cw, fmaf( g0.x, sw, fi0));
        fr1 = fmaf(g1.x, cw, fmaf(-g1.y, sw, fr1));
        fi1 = fmaf(g1.y, cw, fmaf( g1.x, sw, fi1));
        float cn = cw * cd - sw * sd;
        sw = fmaf(cw, sd, sw * cd);  cw = cn;
    }
    int base = bc * 1024 + (s * 16 + kq * 2) * 2;
    g_F[base] = fr0; g_F[base + 1] = fi0; g_F[base + 2] = fr1; g_F[base + 3] = fi1;
}

// per-mode 16x64 @ 64x64 complex mix. block per (s,kx)
__global__ void __launch_bounds__(256) k_spec(const float* __restrict__ w1r, const float* __restrict__ w1i,
                                              const float* __restrict__ w2r, const float* __restrict__ w2i,
                                              int l) {
    __shared__ float Wr[4096], Wi[4096], Ar[1024], Ai[1024];
    int s = blockIdx.x >> 4, kx = blockIdx.x & 15;
    int m = (s < 16) ? s : s - 16;
    long off = (long)l * Cn * Cn * 256 + m * 16 + kx;
    const float* wr = ((s < 16) ? w1r : w2r) + off;
    const float* wi = ((s < 16) ? w1i : w2i) + off;
    for (int t = threadIdx.x; t < 4096; t += 256) { Wr[t] = wr[(long)t * 256]; Wi[t] = wi[(long)t * 256]; }
    int mo = (s * 16 + kx) * 2;
    for (int t = threadIdx.x; t < 1024; t += 256) { Ar[t] = g_F[t * 1024 + mo]; Ai[t] = g_F[t * 1024 + mo + 1]; }
    __syncthreads();
    int o = threadIdx.x & 63, bq = threadIdx.x >> 6;
    float orr[4], oii[4];
    #pragma unroll
    for (int u = 0; u < 4; u++) { orr[u] = 0.f; oii[u] = 0.f; }
    for (int i = 0; i < 64; i++) {
        float wrv = Wr[i * 64 + o], wiv = Wi[i * 64 + o];
        #pragma unroll
        for (int u = 0; u < 4; u++) {
            float arv = Ar[(bq * 4 + u) * 64 + i], aiv = Ai[(bq * 4 + u) * 64 + i];
            orr[u] = fmaf(arv, wrv, fmaf(-aiv, wiv, orr[u]));
            oii[u] = fmaf(arv, wiv, fmaf( aiv, wrv, oii[u]));
        }
    }
    #pragma unroll
    for (int u = 0; u < 4; u++) {
        int b = bq * 4 + u;
        g_F2[(b * 64 + o) * 1024 + mo]     = orr[u];
        g_F2[(b * 64 + o) * 1024 + mo + 1] = oii[u];
    }
}

// 32 ky -> 256 h, with c_kx and 1/65536 folded. block per (b,o), 128 thr x 2 h
__global__ void __launch_bounds__(128) k_inv_h() {
    __shared__ float Fs[1024], outp[8192], tc[256], ts[256];
    int tid = threadIdx.x, bo = blockIdx.x;
    const float* fp = g_F2 + bo * 1024;
    for (int i = tid; i < 1024; i += 128) Fs[i] = fp[i];
    tc[tid] = g_ct[tid]; ts[tid] = g_st[tid];
    tc[tid + 128] = g_ct[tid + 128]; ts[tid + 128] = g_st[tid + 128];
    __syncthreads();
    int h0 = tid, h1 = tid + 128;
    float ac[16][4];
    #pragma unroll
    for (int k = 0; k < 16; k++) { ac[k][0]=0.f; ac[k][1]=0.f; ac[k][2]=0.f; ac[k][3]=0.f; }
    for (int s = 0; s < 32; s++) {
        int ky = (s < 16) ? s : s + 224;
        int t0 = (ky * h0) & 255, t1 = (ky * h1) & 255;
        float c0 = tc[t0], s0 = ts[t0], c1 = tc[t1], s1 = ts[t1];
        #pragma unroll
        for (int k = 0; k < 16; k++) {
            float2 f = *(const float2*)&Fs[(s * 16 + k) * 2];
            ac[k][0] = fmaf(f.x, c0, fmaf(-f.y, s0, ac[k][0]));
            ac[k][1] = fmaf(f.y, c0, fmaf( f.x, s0, ac[k][1]));
            ac[k][2] = fmaf(f.x, c1, fmaf(-f.y, s1, ac[k][2]));
            ac[k][3] = fmaf(f.y, c1, fmaf( f.x, s1, ac[k][3]));
        }
    }
    #pragma unroll
    for (int k = 0; k < 16; k++) {
        float sc = (k == 0 ? 1.f : 2.f) * (1.f / 65536.f);
        outp[(k * 2) * 256 + h0]     = ac[k][0] * sc;
        outp[(k * 2 + 1) * 256 + h0] = ac[k][1] * sc;
        outp[(k * 2) * 256 + h1]     = ac[k][2] * sc;
        outp[(k * 2 + 1) * 256 + h1] = ac[k][3] * sc;
    }
    __syncthreads();
    float* gp = g_Gi + bo * 8192;
    for (int i = tid; i < 8192; i += 128) gp[i] = outp[i];
}

// fused inv w-DFT + skip conv + BN + gelu + residual, in place. block per (b,h)
__global__ void __launch_bounds__(256, 2) k_fuse(const float* __restrict__ skw, const float* __restrict__ skb,
                                                 const float* __restrict__ bng, const float* __restrict__ bnb,
                                                 const float* __restrict__ bnm, const float* __restrict__ bnv,
                                                 int l) {
    extern __shared__ float sm[];
    float* xs  = sm;              // 64*264
    float* sws = xs + 16896;      // 4096
    float* gis = sws + 4096;      // 2048
    float* tc  = gis + 2048;      // 256
    float* ts  = tc + 256;        // 256
    float* bnA = ts + 256;        // 64
    float* bnB = bnA + 64;        // 64
    float* sbb = bnB + 64;        // 64
    int tid = threadIdx.x;
    int b = blockIdx.x >> 8, h = blockIdx.x & 255;
    float* xp = g_x + b * 64 * HWn + h * 256;
    for (int c = 0; c < 64; c++) xs[c * 264 + tid] = xp[c * HWn + tid];
    for (int i = tid; i < 4096; i += 256) sws[i] = skw[l * 4096 + i];
    for (int i = tid; i < 2048; i += 256)
        gis[i] = g_Gi[(b * 64 + (i >> 5)) * 8192 + (i & 31) * 256 + h];
    tc[tid] = g_ct[tid];  ts[tid] = g_st[tid];
    if (tid < 64) {
        float A = bng[l * 64 + tid] * rsqrtf(bnv[l * 64 + tid] + 1e-5f);
        bnA[tid] = A;
        bnB[tid] = fmaf(-bnm[l * 64 + tid], A, bnb[l * 64 + tid]);
        sbb[tid] = skb[l * 64 + tid];
    }
    __syncthreads();
    int wb = (tid & 63) * 4, ob = (tid >> 6) * 16;
    float acc[16][4];
    #pragma unroll
    for (int i = 0; i < 16; i++) {
        float bias = sbb[ob + i];
        acc[i][0] = bias; acc[i][1] = bias; acc[i][2] = bias; acc[i][3] = bias;
    }
    for (int c = 0; c < 64; c++) {
        float4 xv = *(const float4*)&xs[c * 264 + wb];
        #pragma unroll
        for (int i = 0; i < 16; i++) {
            float s = sws[(ob + i) * 64 + c];
            acc[i][0] = fmaf(xv.x, s, acc[i][0]);
            acc[i][1] = fmaf(xv.y, s, acc[i][1]);
            acc[i][2] = fmaf(xv.z, s, acc[i][2]);
            acc[i][3] = fmaf(xv.w, s, acc[i][3]);
        }
    }
    #pragma unroll 2
    for (int kx = 0; kx < 16; kx++) {
        float c0 = tc[(kx * wb) & 255],       s0 = ts[(kx * wb) & 255];
        float c1 = tc[(kx * (wb + 1)) & 255], s1 = ts[(kx * (wb + 1)) & 255];
        float c2 = tc[(kx * (wb + 2)) & 255], s2 = ts[(kx * (wb + 2)) & 255];
        float c3 = tc[(kx * (wb + 3)) & 255], s3 = ts[(kx * (wb + 3)) & 255];
        #pragma unroll
        for (int i = 0; i < 16; i++) {
            float gr = gis[(ob + i) * 32 + kx * 2];
            float gi = gis[(ob + i) * 32 + kx * 2 + 1];
            acc[i][0] = fmaf(gr, c0, fmaf(-gi, s0, acc[i][0]));
            acc[i][1] = fmaf(gr, c1, fmaf(-gi, s1, acc[i][1]));
            acc[i][2] = fmaf(gr, c2, fmaf(-gi, s2, acc[i][2]));
            acc[i][3] = fmaf(gr, c3, fmaf(-gi, s3, acc[i][3]));
        }
    }
    #pragma unroll
    for (int i = 0; i < 16; i++) {
        int o = ob + i;
        float A = bnA[o], Bc = bnB[o];
        float4 ov;
        ov.x = gelu(fmaf(acc[i][0], A, Bc)) + xs[o * 264 + wb];
        ov.y = gelu(fmaf(acc[i][1], A, Bc)) + xs[o * 264 + wb + 1];
        ov.z = gelu(fmaf(acc[i][2], A, Bc)) + xs[o * 264 + wb + 2];
        ov.w = gelu(fmaf(acc[i][3], A, Bc)) + xs[o * 264 + wb + 3];
        *(float4*)&xp[o * HWn + wb] = ov;
    }
}

// proj conv + gelu + partial mean over w. block per (b,h)
__global__ void __launch_bounds__(256) k_proj(const float* __restrict__ pw, const float* __restrict__ pb) {
    __shared__ float pws[4096], pbs[64], wsum[64][8];
    int tid = threadIdx.x;
    int b = blockIdx.x >> 8, h = blockIdx.x & 255;
    for (int i = tid; i < 4096; i += 256) pws[i] = pw[i];
    if (tid < 64) pbs[tid] = pb[tid];
    __syncthreads();
    const float* xp = g_x + b * 64 * HWn + h * 256 + tid;
    float xv[64];
    #pragma unroll
    for (int c = 0; c < 64; c++) xv[c] = xp[c * HWn];
    int lane = tid & 31, wid = tid >> 5;
    for (int o = 0; o < 64; o++) {
        float a = pbs[o];
        #pragma unroll
        for (int c = 0; c < 64; c++) a = fmaf(xv[c], pws[o * 64 + c], a);
        a = gelu(a);
        #pragma unroll
        for (int off = 16; off; off >>= 1) a += __shfl_down_sync(0xffffffffu, a, off);
        if (lane == 0) wsum[o][wid] = a;
    }
    __syncthreads();
    if (tid < 64) {
        float s = 0.f;
        #pragma unroll
        for (int j = 0; j < 8; j++) s += wsum[tid][j];
        g_part[(b * 64 + tid) * 256 + h] = s;
    }
}

__global__ void __launch_bounds__(128) k_head(const float* __restrict__ env, const float* __restrict__ d1d,
    const float* __restrict__ dw1, const float* __restrict__ db1,
    const float* __restrict__ dw2, const float* __restrict__ db2,
    const float* __restrict__ dw3, const float* __restrict__ db3,
    const float* __restrict__ iw1, const float* __restrict__ ib1,
    const float* __restrict__ iw2, const float* __restrict__ ib2,
    const float* __restrict__ iw3, const float* __restrict__ ib3,
    float* __restrict__ out) {
    __shared__ float feat[108], h1[128], h2[64];
    int b = blockIdx.x, t = threadIdx.x;
    if (t < 64) {
        float s = 0.f;
        const float* pp = g_part + (b * 64 + t) * 256;
        for (int h = 0; h < 256; h++) s += pp[h];
        feat[t] = s * (1.0f / 65536.0f);
    } else if (t < 104) feat[t] = env[b * 40 + t - 64];
    else if (t < 108)   feat[t] = d1d[b * 4 + t - 104];
    __syncthreads();
    { float a = db1[t];
      for (int k = 0; k < 108; k++) a = fmaf(feat[k], dw1[t * 108 + k], a);
      h1[t] = gelu(a); }
    __syncthreads();
    if (t < 64) { float a = db2[t];
      for (int k = 0; k < 128; k++) a = fmaf(h1[k], dw2[t * 128 + k], a);
      h2[t] = gelu(a); }
    __syncthreads();
    if (t < 8) { float a = db3[t];
      for (int k = 0; k < 64; k++) a = fmaf(h2[k], dw3[t * 64 + k], a);
      out[b * 8 + t] = a; }
    __syncthreads();
    { float a = ib1[t];
      for (int k = 0; k < 108; k++) a = fmaf(feat[k], iw1[t * 108 + k], a);
      h1[t] = gelu(a); }
    __syncthreads();
    if (t < 64) { float a = ib2[t];
      for (int k = 0; k < 128; k++) a = fmaf(h1[k], iw2[t * 128 + k], a);
      h2[t] = gelu(a); }
    __syncthreads();
    if (t < 4) { float a = ib3[t];
      for (int k = 0; k < 64; k++) a = fmaf(h2[k], iw3[t * 64 + k], a);
      out[128 + b * 4 + t] = a; }
}

extern "C" void kernel_launch(void* const* d_in, const int* in_sizes, int n_in,
                              void* d_out, int out_size) {
    const float* grid_in = (const float*)d_in[0];
    const float* env  = (const float*)d_in[1];
    const float* d1d  = (const float*)d_in[2];
    const float* lw   = (const float*)d_in[3];
    const float* lb   = (const float*)d_in[4];
    const float* w1r  = (const float*)d_in[5];
    const float* w1i  = (const float*)d_in[6];
    const float* w2r  = (const float*)d_in[7];
    const float* w2i  = (const float*)d_in[8];
    const float* skw  = (const float*)d_in[9];
    const float* skb  = (const float*)d_in[10];
    const float* bng  = (const float*)d_in[11];
    const float* bnb  = (const float*)d_in[12];
    const float* bnm  = (const float*)d_in[13];
    const float* bnv  = (const float*)d_in[14];
    const float* pw   = (const float*)d_in[15];
    const float* pb   = (const float*)d_in[16];
    const float* dw1  = (const float*)d_in[17];
    const float* db1  = (const float*)d_in[18];
    const float* dw2  = (const float*)d_in[19];
    const float* db2  = (const float*)d_in[20];
    const float* dw3  = (const float*)d_in[21];
    const float* db3  = (const float*)d_in[22];
    const float* iw1  = (const float*)d_in[23];
    const float* ib1  = (const float*)d_in[24];
    const float* iw2  = (const float*)d_in[25];
    const float* ib2  = (const float*)d_in[26];
    const float* iw3  = (const float*)d_in[27];
    const float* ib3  = (const float*)d_in[28];
    float* out = (float*)d_out;

    static bool attr_done = false;
    if (!attr_done) {
        cudaFuncSetAttribute(k_fwd_w, cudaFuncAttributeMaxDynamicSharedMemorySize, 65792);
        cudaFuncSetAttribute(k_fuse,  cudaFuncAttributeMaxDynamicSharedMemorySize, 94976);
        attr_done = true;
    }

    k_twiddle<<<1, 256>>>();
    k_lift<<<4096, 256>>>(grid_in, lw, lb);
    for (int l = 0; l < 4; l++) {
        k_fwd_w<<<4096, 128, 65792>>>();
        k_fwd_h<<<1024, 256>>>();
        k_spec<<<512, 256>>>(w1r, w1i, w2r, w2i, l);
        k_inv_h<<<1024, 128>>>();
        k_fuse<<<4096, 256, 94976>>>(skw, skb, bng, bnb, bnm, bnv, l);
    }
    k_proj<<<4096, 256>>>(pw, pb);
    k_head<<<16, 128>>>(env, d1d, dw1, db1, dw2, db2, dw3, db3,
                        iw1, ib1, iw2, ib2, iw3, ib3, out);
}